// round 15
// baseline (speedup 1.0000x reference)
#include <cuda_runtime.h>
#include <cuda_bf16.h>

#define N_B 32
#define C_B 64
#define D_B 128
#define MAT 16384
#define NK_TOT 2048
#define TPB 256                  // k_mix threads
#define ATPB 512                 // k_attn threads (16 warps, 4x4 warp grid)

// fp16 tile geometry for k_attn
#define SSTR 136                 // halves per row (272B, conflict-free for ldmatrix)
#define TILEB 34816              // one 128x136 b16 tile
#define DSM (4*TILEB)            // 139264 B dynamic smem (Q, K, St/e~, X'''/P)
#define PSCL 0.03125f            // P storage scale (overflow guard)
#define PSCLI 32.0f

typedef unsigned long long u64;
typedef unsigned int u32;
typedef unsigned short u16;

__device__ float g_rv[NK_TOT*D_B];
// Q/K as single fp16 (k_mix output)
__device__ u16 g_Qf[NK_TOT*MAT], g_Kf[NK_TOT*MAT];

// ---------- f32x2 helpers ----------
__device__ __forceinline__ u64 bcast2(float x){
    u64 r; asm("mov.b64 %0, {%1, %1};" : "=l"(r) : "r"(__float_as_uint(x))); return r;
}
__device__ __forceinline__ u64 pack2(float a, float b){
    u64 r; asm("mov.b64 %0, {%1, %2};" : "=l"(r) : "r"(__float_as_uint(a)), "r"(__float_as_uint(b))); return r;
}
__device__ __forceinline__ u64 ffma2(u64 a, u64 b, u64 c){
    u64 d; asm("fma.rn.f32x2 %0, %1, %2, %3;" : "=l"(d) : "l"(a), "l"(b), "l"(c)); return d;
}
__device__ __forceinline__ u64 add2(u64 a, u64 b){
    u64 d; asm("add.rn.f32x2 %0, %1, %2;" : "=l"(d) : "l"(a), "l"(b)); return d;
}
__device__ __forceinline__ u64 mul2(u64 a, u64 b){
    u64 d; asm("mul.rn.f32x2 %0, %1, %2;" : "=l"(d) : "l"(a), "l"(b)); return d;
}
__device__ __forceinline__ void unpack2(u64 v, float& lo, float& hi){
    u32 a, b; asm("mov.b64 {%0, %1}, %2;" : "=r"(a), "=r"(b) : "l"(v));
    lo = __uint_as_float(a); hi = __uint_as_float(b);
}
__device__ __forceinline__ void unpack2u(u64 v, u32& a, u32& b){
    asm("mov.b64 {%0, %1}, %2;" : "=r"(a), "=r"(b) : "l"(v));
}
union F4U { float4 f; u64 u[2]; };
__device__ __forceinline__ float clip1(float x){ return fminf(1.f, fmaxf(-1.f, x)); }

// fma-pipe exp (magic rounding + deg-5 Taylor), underflow-clamped
__device__ __forceinline__ u64 exp_pair(u64 xb, u64 kL2E, u64 kMAG, u64 kNMAG, u64 kN1,
                                        u64 kC5, u64 kC4, u64 kC3, u64 kC2, u64 kC1, u64 kONE){
    u64 y = mul2(xb, kL2E);
    u64 z = add2(y, kMAG);
    u64 t = add2(z, kNMAG);
    u64 f = ffma2(t, kN1, y);
    u64 p = ffma2(kC5, f, kC4);
    p = ffma2(p, f, kC3); p = ffma2(p, f, kC2); p = ffma2(p, f, kC1); p = ffma2(p, f, kONE);
    u32 zl, zh; unpack2u(z, zl, zh);
    int n0 = max((int)(zl - 0x4B400000u), -127), n1 = max((int)(zh - 0x4B400000u), -127);
    u64 s; asm("mov.b64 %0, {%1, %2};" : "=l"(s)
               : "r"((u32)(n0 + 127) << 23), "r"((u32)(n1 + 127) << 23));
    return mul2(p, s);
}

// ---------- async / mma primitives (arch-generic, sm_80+) ----------
__device__ __forceinline__ void cp16(u32 s, const void* g){
    asm volatile("cp.async.cg.shared.global [%0], [%1], 16;" :: "r"(s), "l"(g));
}
__device__ __forceinline__ void cp_commit(){ asm volatile("cp.async.commit_group;"); }
__device__ __forceinline__ void cp_wait0(){ asm volatile("cp.async.wait_group 0;"); }
__device__ __forceinline__ void cp_wait1(){ asm volatile("cp.async.wait_group 1;"); }
__device__ __forceinline__ u32 smem_u32(const void* p){
    u32 a; asm("{ .reg .u64 t; cvta.to.shared.u64 t, %1; cvt.u32.u64 %0, t; }" : "=r"(a) : "l"(p));
    return a;
}
__device__ __forceinline__ void ldsm4(u32 a, u32* r){
    asm volatile("ldmatrix.sync.aligned.m8n8.x4.shared.b16 {%0,%1,%2,%3}, [%4];"
        : "=r"(r[0]), "=r"(r[1]), "=r"(r[2]), "=r"(r[3]) : "r"(a));
}
__device__ __forceinline__ void ldsm4t(u32 a, u32* r){
    asm volatile("ldmatrix.sync.aligned.m8n8.x4.trans.shared.b16 {%0,%1,%2,%3}, [%4];"
        : "=r"(r[0]), "=r"(r[1]), "=r"(r[2]), "=r"(r[3]) : "r"(a));
}
__device__ __forceinline__ void ldsm2(u32 a, u32* r){
    asm volatile("ldmatrix.sync.aligned.m8n8.x2.shared.b16 {%0,%1}, [%2];"
        : "=r"(r[0]), "=r"(r[1]) : "r"(a));
}
__device__ __forceinline__ void ldsm2t(u32 a, u32* r){
    asm volatile("ldmatrix.sync.aligned.m8n8.x2.trans.shared.b16 {%0,%1}, [%2];"
        : "=r"(r[0]), "=r"(r[1]) : "r"(a));
}
__device__ __forceinline__ void mmah(float* d, const u32* a, const u32* b){
    asm volatile("mma.sync.aligned.m16n8k16.row.col.f32.f16.f16.f32 "
        "{%0,%1,%2,%3},{%4,%5,%6,%7},{%8,%9},{%0,%1,%2,%3};"
        : "+f"(d[0]), "+f"(d[1]), "+f"(d[2]), "+f"(d[3])
        : "r"(a[0]), "r"(a[1]), "r"(a[2]), "r"(a[3]), "r"(b[0]), "r"(b[1]));
}
// pack two floats to f16x2 (first arg in low half)
__device__ __forceinline__ u32 cvt2h(float lo, float hi){
    u32 r; asm("cvt.rn.f16x2.f32 %0, %1, %2;" : "=r"(r) : "f"(hi), "f"(lo)); return r;
}

// warp-tile fp16 single-product matmul, 32x32 warp tile: acc[2][4][4].
// am/bm: 0 = plain row-major fragment, 1 = transposed (ldmatrix.trans).
__device__ __forceinline__ void wmm_h(u32 aB, u32 bB, int am, int bm,
                                      int wm, int wn, int l, float acc[2][4][4]){
    #pragma unroll
    for (int mt = 0; mt < 2; mt++)
        #pragma unroll
        for (int nt = 0; nt < 4; nt++)
            #pragma unroll
            for (int q = 0; q < 4; q++) acc[mt][nt][q] = 0.f;
    #pragma unroll
    for (int ks = 0; ks < 8; ks++){
        int k0 = ks*16;
        u32 Ah[2][4], Bh[4][2];
        #pragma unroll
        for (int mt = 0; mt < 2; mt++){
            int i0 = wm*32 + mt*16;
            u32 ad;
            if (am == 0) ad = aB + (u32)(((i0 + (l&7) + ((l>>3)&1)*8)*SSTR + k0 + (l>>4)*8)*2);
            else         ad = aB + (u32)(((k0 + (l>>4)*8 + (l&7))*SSTR + i0 + ((l>>3)&1)*8)*2);
            if (am == 0) ldsm4(ad, Ah[mt]);
            else         ldsm4t(ad, Ah[mt]);
        }
        #pragma unroll
        for (int nt = 0; nt < 4; nt++){
            int j0 = wn*32 + nt*8;
            u32 bd;
            if (bm == 0) bd = bB + (u32)(((j0 + (l&7))*SSTR + k0 + ((l>>3)&1)*8)*2);
            else         bd = bB + (u32)(((k0 + (l&15))*SSTR + j0)*2);
            if (bm == 0) ldsm2(bd, Bh[nt]);
            else         ldsm2t(bd, Bh[nt]);
        }
        #pragma unroll
        for (int mt = 0; mt < 2; mt++)
            #pragma unroll
            for (int nt = 0; nt < 4; nt++)
                mmah(acc[mt][nt], Ah[mt], Bh[nt]);
    }
}

// store warp acc -> single fp16 tile, optional per-column scale + global scale
__device__ __forceinline__ void store_acc_h(char* smc, u32 dstOff, int wm, int wn, int l,
                                            float acc[2][4][4], const float* colscale,
                                            float gs){
    int r0 = l >> 2, c0 = (l & 3)*2;
    #pragma unroll
    for (int mt = 0; mt < 2; mt++)
        #pragma unroll
        for (int nt = 0; nt < 4; nt++){
            int row = wm*32 + mt*16 + r0, col = wn*32 + nt*8 + c0;
            float s0 = gs, s1 = gs;
            if (colscale){ s0 *= colscale[col]; s1 *= colscale[col+1]; }
            #pragma unroll
            for (int h = 0; h < 2; h++){
                u32 hp = cvt2h(acc[mt][nt][h*2] * s0, acc[mt][nt][h*2+1] * s1);
                *(u32*)(smc + dstOff + (u32)((((row + h*8)*SSTR) + col)*2)) = hp;
            }
        }
}

// cp.async one fp16 tensor into a tile region (ATPB threads)
__device__ __forceinline__ void pf_tile(u32 dst, const u16* __restrict__ src, int tid){
    for (int g = tid; g < 2048; g += ATPB){
        int m = g >> 4, c = (g & 15)*8;
        cp16(dst + (u32)((m*SSTR + c)*2), src + m*128 + c);
    }
}

// ============================================================================
__global__ void k_rinv(const float* __restrict__ in){
    int nk = blockIdx.x, t = threadIdx.x;
    float v = in[(size_t)nk*MAT + t*D_B + t];
    g_rv[nk*D_B + t] = rsqrtf(fmaxf(fabsf(v), 1e-4f));
}

// fused cov2cor + channel mixing; cp.async double-buffered staging.
// Outputs single fp16 Q/K.
__global__ __launch_bounds__(256, 1) void k_mix(const float* __restrict__ inp,
                                                const float* __restrict__ wq,
                                                const float* __restrict__ wk){
    __shared__ float sWQ[C_B*C_B], sWK[C_B*C_B];
    __shared__ float sX [2][8*D_B];
    __shared__ float sRV[2][8*D_B];
    int tid = threadIdx.x, n = blockIdx.y, irow = blockIdx.x;
    int tx = tid & 31, ty = tid >> 5, k0 = ty*8;
    u32 sxA[2] = { smem_u32(&sX[0][0]),  smem_u32(&sX[1][0])  };
    u32 rvA[2] = { smem_u32(&sRV[0][0]), smem_u32(&sRV[1][0]) };

    {
        int cl = tid >> 5, jj = (tid & 31)*4;
        cp16(sxA[0] + (u32)((cl*D_B + jj)*4),
             inp + ((size_t)(n*C_B + cl))*MAT + irow*D_B + jj);
        int idx = tid*4, cl2 = idx >> 7, j2 = idx & 127;
        cp16(rvA[0] + (u32)(idx*4), g_rv + ((size_t)(n*C_B + cl2))*D_B + j2);
        cp_commit();
    }
    for (int i = tid; i < C_B*C_B; i += 256){ sWQ[i] = wq[i]; sWK[i] = wk[i]; }

    u64 aQ[4][4], aK[4][4];
    #pragma unroll
    for (int p = 0; p < 4; p++)
        #pragma unroll
        for (int q = 0; q < 4; q++){ aQ[p][q] = 0ull; aK[p][q] = 0ull; }

    for (int cb = 0; cb < 8; cb++){
        int cur = cb & 1, cc = cb*8;
        if (cb < 7){
            int nb = cur ^ 1, ncc = cc + 8;
            int cl = tid >> 5, jj = (tid & 31)*4;
            cp16(sxA[nb] + (u32)((cl*D_B + jj)*4),
                 inp + ((size_t)(n*C_B + ncc + cl))*MAT + irow*D_B + jj);
            int idx = tid*4, cl2 = idx >> 7, j2 = idx & 127;
            cp16(rvA[nb] + (u32)(idx*4), g_rv + ((size_t)(n*C_B + ncc + cl2))*D_B + j2);
            cp_commit();
            cp_wait1();
        } else {
            cp_wait0();
        }
        __syncthreads();
        {
            int cl = tid >> 5, jj = (tid & 31)*4;
            float4 v = *(float4*)&sX[cur][cl*D_B + jj];
            float ri = sRV[cur][cl*D_B + irow];
            v.x = clip1(v.x*ri*sRV[cur][cl*D_B + jj+0]);
            v.y = clip1(v.y*ri*sRV[cur][cl*D_B + jj+1]);
            v.z = clip1(v.z*ri*sRV[cur][cl*D_B + jj+2]);
            v.w = clip1(v.w*ri*sRV[cur][cl*D_B + jj+3]);
            *(float4*)&sX[cur][cl*D_B + jj] = v;
        }
        __syncthreads();
        #pragma unroll
        for (int cl = 0; cl < 8; cl++){
            int c = cc + cl;
            float4 xv = *(const float4*)&sX[cur][cl*D_B + tx*4];
            u64 xx[4] = { bcast2(xv.x), bcast2(xv.y), bcast2(xv.z), bcast2(xv.w) };
            F4U q0, q1, kk0, kk1;
            q0.f = *(const float4*)&sWQ[c*C_B + k0];  q1.f = *(const float4*)&sWQ[c*C_B + k0 + 4];
            kk0.f = *(const float4*)&sWK[c*C_B + k0]; kk1.f = *(const float4*)&sWK[c*C_B + k0 + 4];
            u64 bq[4] = { q0.u[0], q0.u[1], q1.u[0], q1.u[1] };
            u64 bk[4] = { kk0.u[0], kk0.u[1], kk1.u[0], kk1.u[1] };
            #pragma unroll
            for (int p = 0; p < 4; p++)
                #pragma unroll
                for (int q = 0; q < 4; q++){
                    aQ[p][q] = ffma2(xx[p], bq[q], aQ[p][q]);
                    aK[p][q] = ffma2(xx[p], bk[q], aK[p][q]);
                }
        }
        __syncthreads();
    }
    #pragma unroll
    for (int q = 0; q < 4; q++)
        #pragma unroll
        for (int h = 0; h < 2; h++){
            int k = k0 + q*2 + h;
            float vq[4], vk[4];
            #pragma unroll
            for (int p = 0; p < 4; p++){
                float lo, hi;
                unpack2(aQ[p][q], lo, hi); vq[p] = h ? hi : lo;
                unpack2(aK[p][q], lo, hi); vk[p] = h ? hi : lo;
            }
            size_t base = ((size_t)(n*C_B + k))*MAT + irow*D_B + tx*4;
            *(uint2*)&g_Qf[base] = make_uint2(cvt2h(vq[0], vq[1]), cvt2h(vq[2], vq[3]));
            *(uint2*)&g_Kf[base] = make_uint2(cvt2h(vk[0], vk[1]), cvt2h(vk[2], vk[3]));
        }
}

// ============================================================================
// k_attn: PERSISTENT, 512 threads. ALL matmuls fp16 single-product.
//   St = Q^T K; Apre = St^T K; e = exp(Apre - max); sr from rowsums;
//   e~ = e*diag(sr); X''' = clip(cov2cor(inp)); P = e~ X'''; O = P e~^T;
//   out = inp + lam*32*sr_i*sr_j*O
// Buffers (1 fp16 tile each):
//   B0: Q(i) [dead after mm1 -> prefetch Q(i+1)]
//   B1: K(i) [dead after mm2 -> prefetch K(i+1)]
//   B2: St -> e~    B3: X''' -> P/32
// ============================================================================
__global__ __launch_bounds__(ATPB, 1) void k_attn(const float* __restrict__ inp,
                                                  const float* __restrict__ lam,
                                                  float* __restrict__ out){
    extern __shared__ char smc[];
    u32 sb = smem_u32(smc);
    u32 B0 = sb, B1 = sb + TILEB, B2 = sb + 2*TILEB, B3 = sb + 3*TILEB;
    __shared__ float s_rv[D_B], s_sr[D_B], s_dia[D_B], s_part[D_B][4], s_red[20];
    int tid = threadIdx.x, w = tid >> 5, l = tid & 31;
    int wm = w >> 2, wn = w & 3;
    int r0 = l >> 2, c0 = (l & 3)*2;
    int stride = gridDim.x;

    {
        size_t gb0 = (size_t)blockIdx.x * MAT;
        pf_tile(B0, g_Qf + gb0, tid);
        pf_tile(B1, g_Kf + gb0, tid);
        cp_commit();
    }

    for (int nk = blockIdx.x; nk < NK_TOT; nk += stride){
        size_t gb = (size_t)nk * MAT;
        int nk2 = nk + stride;
        if (tid < D_B) s_rv[tid] = g_rv[nk*D_B + tid];
        cp_wait0();
        __syncthreads();

        float acc[2][4][4];
        wmm_h(B0, B1, 1, 1, wm, wn, l, acc);   // St = Q^T K
        store_acc_h(smc, B2 - sb, wm, wn, l, acc, 0, 1.0f);
        __syncthreads();

        if (nk2 < NK_TOT){                     // prefetch Q(i+1)
            pf_tile(B0, g_Qf + (size_t)nk2*MAT, tid);
            cp_commit();
        }

        wmm_h(B2, B1, 1, 1, wm, wn, l, acc);   // Apre = St^T K
        float mx = -3.4e38f;
        #pragma unroll
        for (int mt = 0; mt < 2; mt++)
            #pragma unroll
            for (int nt = 0; nt < 4; nt++)
                #pragma unroll
                for (int q = 0; q < 4; q++) mx = fmaxf(mx, acc[mt][nt][q]);
        #pragma unroll
        for (int o = 16; o; o >>= 1) mx = fmaxf(mx, __shfl_xor_sync(0xffffffffu, mx, o));
        if (l == 0) s_red[w] = mx;
        __syncthreads();
        if (tid == 0){
            float m2 = s_red[0];
            #pragma unroll
            for (int q = 1; q < 16; q++) m2 = fmaxf(m2, s_red[q]);
            s_red[16] = m2;
        }
        if (nk2 < NK_TOT){                     // prefetch K(i+1)
            pf_tile(B1, g_Kf + (size_t)nk2*MAT, tid);
            cp_commit();
        }
        __syncthreads();
        float bmax = s_red[16];
        {   // exp (all-poly, fma pipe) in place + row partial sums
            const u64 kL2E = bcast2(1.4426950408889634f), kMAG = bcast2(12582912.0f),
                      kNMAG = bcast2(-12582912.0f), kN1 = bcast2(-1.0f),
                      kC5 = bcast2(1.3333558146e-3f), kC4 = bcast2(9.6181291076e-3f),
                      kC3 = bcast2(5.5504108664e-2f), kC2 = bcast2(2.4022650695e-1f),
                      kC1 = bcast2(6.9314718055e-1f), kONE = bcast2(1.0f),
                      kNB = bcast2(-bmax);
            float part[2][2] = {};
            #pragma unroll
            for (int mt = 0; mt < 2; mt++)
                #pragma unroll
                for (int nt = 0; nt < 4; nt++){
                    u64 p0 = exp_pair(add2(pack2(acc[mt][nt][0], acc[mt][nt][1]), kNB),
                                      kL2E,kMAG,kNMAG,kN1,kC5,kC4,kC3,kC2,kC1,kONE);
                    u64 p1 = exp_pair(add2(pack2(acc[mt][nt][2], acc[mt][nt][3]), kNB),
                                      kL2E,kMAG,kNMAG,kN1,kC5,kC4,kC3,kC2,kC1,kONE);
                    unpack2(p0, acc[mt][nt][0], acc[mt][nt][1]);
                    unpack2(p1, acc[mt][nt][2], acc[mt][nt][3]);
                    part[mt][0] += acc[mt][nt][0] + acc[mt][nt][1];
                    part[mt][1] += acc[mt][nt][2] + acc[mt][nt][3];
                }
            #pragma unroll
            for (int mt = 0; mt < 2; mt++)
                #pragma unroll
                for (int h = 0; h < 2; h++){
                    float t = part[mt][h];
                    t += __shfl_xor_sync(0xffffffffu, t, 1);
                    t += __shfl_xor_sync(0xffffffffu, t, 2);
                    if ((l & 3) == 0) s_part[wm*32 + mt*16 + h*8 + r0][wn] = t;
                }
        }
        // X''' = clip(inp*rv_i*rv_j) straight from gmem -> B3 (fp16)
        for (int e = tid; e < 4096; e += ATPB){
            int i = e >> 5, j = (e & 31)*4;
            float4 v = *(const float4*)&inp[gb + i*128 + j];
            float ri = s_rv[i];
            v.x = clip1(v.x*ri*s_rv[j+0]); v.y = clip1(v.y*ri*s_rv[j+1]);
            v.z = clip1(v.z*ri*s_rv[j+2]); v.w = clip1(v.w*ri*s_rv[j+3]);
            u32 off = (B3 - sb) + (u32)((i*SSTR + j)*2);
            *(u32*)(smc + off)     = cvt2h(v.x, v.y);
            *(u32*)(smc + off + 4) = cvt2h(v.z, v.w);
        }
        __syncthreads();
        if (tid < D_B)
            s_dia[tid] = s_part[tid][0] + s_part[tid][1] + s_part[tid][2] + s_part[tid][3];
        __syncthreads();
        if (tid < 32){
            float t = s_dia[tid] + s_dia[tid+32] + s_dia[tid+64] + s_dia[tid+96];
            #pragma unroll
            for (int o = 16; o; o >>= 1) t += __shfl_xor_sync(0xffffffffu, t, o);
            if (tid == 0) s_red[17] = t;
        }
        __syncthreads();
        if (tid < D_B){
            float d = fmaxf(fmaxf(s_dia[tid], s_red[17]/100000.0f), 1e-5f);
            s_sr[tid] = rsqrtf(d);
        }
        __syncthreads();
        store_acc_h(smc, B2 - sb, wm, wn, l, acc, s_sr, 1.0f);  // e~ (over St)
        __syncthreads();

        wmm_h(B2, B3, 0, 1, wm, wn, l, acc);             // P = e~ X'''
        __syncthreads();                                 // all warps done reading X'''
        store_acc_h(smc, B3 - sb, wm, wn, l, acc, 0, PSCL);  // P/32 (over X''')
        __syncthreads();

        wmm_h(B3, B2, 0, 0, wm, wn, l, acc);             // O = (P/32) e~^T
        {   // epilogue: out = inp + lam*32*sr_i*sr_j*O
            float lamv = lam[nk & (C_B - 1)] * PSCLI;
            #pragma unroll
            for (int mt = 0; mt < 2; mt++)
                #pragma unroll
                for (int nt = 0; nt < 4; nt++){
                    int row = wm*32 + mt*16 + r0, col = wn*32 + nt*8 + c0;
                    float sc0 = s_sr[col], sc1 = s_sr[col+1];
                    #pragma unroll
                    for (int h = 0; h < 2; h++){
                        int rr = row + h*8;
                        float li = lamv * s_sr[rr];
                        float2 iv = *(const float2*)&inp[gb + rr*128 + col];
                        float2 o;
                        o.x = iv.x + li*sc0*acc[mt][nt][h*2+0];
                        o.y = iv.y + li*sc1*acc[mt][nt][h*2+1];
                        *(float2*)&out[gb + rr*128 + col] = o;
                    }
                }
        }
    }
}

// ============================================================================
extern "C" void kernel_launch(void* const* d_in, const int* in_sizes, int n_in,
                              void* d_out, int out_size){
    const float* inp = (const float*)d_in[0];
    const float* wq  = (const float*)d_in[1];
    const float* wk  = (const float*)d_in[2];
    const float* lam = (const float*)d_in[3];
    float* out = (float*)d_out;

    int nsm = 148;
    cudaDeviceGetAttribute(&nsm, cudaDevAttrMultiProcessorCount, 0);
    if (nsm <= 0 || nsm > NK_TOT) nsm = 148;

    cudaFuncSetAttribute(k_attn, cudaFuncAttributeMaxDynamicSharedMemorySize, DSM);

    k_rinv<<<NK_TOT, D_B>>>(inp);
    k_mix<<<dim3(D_B, N_B), 256>>>(inp, wq, wk);
    k_attn<<<nsm, ATPB, DSM>>>(inp, lam, out);
}

// round 16
// speedup vs baseline: 1.3036x; 1.3036x over previous
#include <cuda_runtime.h>
#include <cuda_bf16.h>

#define N_B 32
#define C_B 64
#define D_B 128
#define MAT 16384
#define NK_TOT 2048
#define TPB 256                  // k_mix + k_attn threads

// fp16 tile geometry for k_attn
#define SSTR 136                 // halves per row (272B, conflict-free for ldmatrix)
#define TILEB 34816              // one 128x136 b16 tile
#define DSM3 (3*TILEB)           // 104448 B dynamic smem -> 2 CTAs/SM
#define PSCL 0.03125f            // P storage scale (overflow guard)
#define PSCLI 32.0f

typedef unsigned long long u64;
typedef unsigned int u32;
typedef unsigned short u16;

__device__ float g_rv[NK_TOT*D_B];
// Q/K as single fp16 (k_mix output)
__device__ u16 g_Qf[NK_TOT*MAT], g_Kf[NK_TOT*MAT];

// ---------- f32x2 helpers ----------
__device__ __forceinline__ u64 bcast2(float x){
    u64 r; asm("mov.b64 %0, {%1, %1};" : "=l"(r) : "r"(__float_as_uint(x))); return r;
}
__device__ __forceinline__ u64 pack2(float a, float b){
    u64 r; asm("mov.b64 %0, {%1, %2};" : "=l"(r) : "r"(__float_as_uint(a)), "r"(__float_as_uint(b))); return r;
}
__device__ __forceinline__ u64 ffma2(u64 a, u64 b, u64 c){
    u64 d; asm("fma.rn.f32x2 %0, %1, %2, %3;" : "=l"(d) : "l"(a), "l"(b), "l"(c)); return d;
}
__device__ __forceinline__ u64 add2(u64 a, u64 b){
    u64 d; asm("add.rn.f32x2 %0, %1, %2;" : "=l"(d) : "l"(a), "l"(b)); return d;
}
__device__ __forceinline__ u64 mul2(u64 a, u64 b){
    u64 d; asm("mul.rn.f32x2 %0, %1, %2;" : "=l"(d) : "l"(a), "l"(b)); return d;
}
__device__ __forceinline__ void unpack2(u64 v, float& lo, float& hi){
    u32 a, b; asm("mov.b64 {%0, %1}, %2;" : "=r"(a), "=r"(b) : "l"(v));
    lo = __uint_as_float(a); hi = __uint_as_float(b);
}
__device__ __forceinline__ void unpack2u(u64 v, u32& a, u32& b){
    asm("mov.b64 {%0, %1}, %2;" : "=r"(a), "=r"(b) : "l"(v));
}
union F4U { float4 f; u64 u[2]; };
__device__ __forceinline__ float clip1(float x){ return fminf(1.f, fmaxf(-1.f, x)); }

// fma-pipe exp (magic rounding + deg-5 Taylor), underflow-clamped
__device__ __forceinline__ u64 exp_pair(u64 xb, u64 kL2E, u64 kMAG, u64 kNMAG, u64 kN1,
                                        u64 kC5, u64 kC4, u64 kC3, u64 kC2, u64 kC1, u64 kONE){
    u64 y = mul2(xb, kL2E);
    u64 z = add2(y, kMAG);
    u64 t = add2(z, kNMAG);
    u64 f = ffma2(t, kN1, y);
    u64 p = ffma2(kC5, f, kC4);
    p = ffma2(p, f, kC3); p = ffma2(p, f, kC2); p = ffma2(p, f, kC1); p = ffma2(p, f, kONE);
    u32 zl, zh; unpack2u(z, zl, zh);
    int n0 = max((int)(zl - 0x4B400000u), -127), n1 = max((int)(zh - 0x4B400000u), -127);
    u64 s; asm("mov.b64 %0, {%1, %2};" : "=l"(s)
               : "r"((u32)(n0 + 127) << 23), "r"((u32)(n1 + 127) << 23));
    return mul2(p, s);
}

// ---------- async / mma primitives (arch-generic, sm_80+) ----------
__device__ __forceinline__ void cp16(u32 s, const void* g){
    asm volatile("cp.async.cg.shared.global [%0], [%1], 16;" :: "r"(s), "l"(g));
}
__device__ __forceinline__ void cp_commit(){ asm volatile("cp.async.commit_group;"); }
__device__ __forceinline__ void cp_wait0(){ asm volatile("cp.async.wait_group 0;"); }
__device__ __forceinline__ void cp_wait1(){ asm volatile("cp.async.wait_group 1;"); }
__device__ __forceinline__ u32 smem_u32(const void* p){
    u32 a; asm("{ .reg .u64 t; cvta.to.shared.u64 t, %1; cvt.u32.u64 %0, t; }" : "=r"(a) : "l"(p));
    return a;
}
__device__ __forceinline__ void ldsm4(u32 a, u32* r){
    asm volatile("ldmatrix.sync.aligned.m8n8.x4.shared.b16 {%0,%1,%2,%3}, [%4];"
        : "=r"(r[0]), "=r"(r[1]), "=r"(r[2]), "=r"(r[3]) : "r"(a));
}
__device__ __forceinline__ void ldsm4t(u32 a, u32* r){
    asm volatile("ldmatrix.sync.aligned.m8n8.x4.trans.shared.b16 {%0,%1,%2,%3}, [%4];"
        : "=r"(r[0]), "=r"(r[1]), "=r"(r[2]), "=r"(r[3]) : "r"(a));
}
__device__ __forceinline__ void ldsm2(u32 a, u32* r){
    asm volatile("ldmatrix.sync.aligned.m8n8.x2.shared.b16 {%0,%1}, [%2];"
        : "=r"(r[0]), "=r"(r[1]) : "r"(a));
}
__device__ __forceinline__ void ldsm2t(u32 a, u32* r){
    asm volatile("ldmatrix.sync.aligned.m8n8.x2.trans.shared.b16 {%0,%1}, [%2];"
        : "=r"(r[0]), "=r"(r[1]) : "r"(a));
}
__device__ __forceinline__ void mmah(float* d, const u32* a, const u32* b){
    asm volatile("mma.sync.aligned.m16n8k16.row.col.f32.f16.f16.f32 "
        "{%0,%1,%2,%3},{%4,%5,%6,%7},{%8,%9},{%0,%1,%2,%3};"
        : "+f"(d[0]), "+f"(d[1]), "+f"(d[2]), "+f"(d[3])
        : "r"(a[0]), "r"(a[1]), "r"(a[2]), "r"(a[3]), "r"(b[0]), "r"(b[1]));
}
// pack two floats to f16x2 (first arg in low half)
__device__ __forceinline__ u32 cvt2h(float lo, float hi){
    u32 r; asm("cvt.rn.f16x2.f32 %0, %1, %2;" : "=r"(r) : "f"(hi), "f"(lo)); return r;
}

// warp-tile fp16 matmul, 64x32 warp tile (8 warps, 2x4 grid): acc[4][4][4].
// am/bm: 0 = plain row-major fragment, 1 = transposed (ldmatrix.trans).
__device__ __forceinline__ void wmm_h(u32 aB, u32 bB, int am, int bm,
                                      int wm, int wn, int l, float acc[4][4][4]){
    #pragma unroll
    for (int mt = 0; mt < 4; mt++)
        #pragma unroll
        for (int nt = 0; nt < 4; nt++)
            #pragma unroll
            for (int q = 0; q < 4; q++) acc[mt][nt][q] = 0.f;
    #pragma unroll
    for (int ks = 0; ks < 8; ks++){
        int k0 = ks*16;
        u32 Ah[4][4], Bh[4][2];
        #pragma unroll
        for (int mt = 0; mt < 4; mt++){
            int i0 = wm*64 + mt*16;
            u32 ad;
            if (am == 0) ad = aB + (u32)(((i0 + (l&7) + ((l>>3)&1)*8)*SSTR + k0 + (l>>4)*8)*2);
            else         ad = aB + (u32)(((k0 + (l>>4)*8 + (l&7))*SSTR + i0 + ((l>>3)&1)*8)*2);
            if (am == 0) ldsm4(ad, Ah[mt]);
            else         ldsm4t(ad, Ah[mt]);
        }
        #pragma unroll
        for (int nt = 0; nt < 4; nt++){
            int j0 = wn*32 + nt*8;
            u32 bd;
            if (bm == 0) bd = bB + (u32)(((j0 + (l&7))*SSTR + k0 + ((l>>3)&1)*8)*2);
            else         bd = bB + (u32)(((k0 + (l&15))*SSTR + j0)*2);
            if (bm == 0) ldsm2(bd, Bh[nt]);
            else         ldsm2t(bd, Bh[nt]);
        }
        #pragma unroll
        for (int mt = 0; mt < 4; mt++)
            #pragma unroll
            for (int nt = 0; nt < 4; nt++)
                mmah(acc[mt][nt], Ah[mt], Bh[nt]);
    }
}

// store warp acc -> single fp16 tile, optional per-column scale + global scale
__device__ __forceinline__ void store_acc_h(char* smc, u32 dstOff, int wm, int wn, int l,
                                            float acc[4][4][4], const float* colscale,
                                            float gs){
    int r0 = l >> 2, c0 = (l & 3)*2;
    #pragma unroll
    for (int mt = 0; mt < 4; mt++)
        #pragma unroll
        for (int nt = 0; nt < 4; nt++){
            int row = wm*64 + mt*16 + r0, col = wn*32 + nt*8 + c0;
            float s0 = gs, s1 = gs;
            if (colscale){ s0 *= colscale[col]; s1 *= colscale[col+1]; }
            #pragma unroll
            for (int h = 0; h < 2; h++){
                u32 hp = cvt2h(acc[mt][nt][h*2] * s0, acc[mt][nt][h*2+1] * s1);
                *(u32*)(smc + dstOff + (u32)((((row + h*8)*SSTR) + col)*2)) = hp;
            }
        }
}

// cp.async one fp16 tensor into a tile region (TPB threads)
__device__ __forceinline__ void pf_tile(u32 dst, const u16* __restrict__ src, int tid){
    for (int g = tid; g < 2048; g += TPB){
        int m = g >> 4, c = (g & 15)*8;
        cp16(dst + (u32)((m*SSTR + c)*2), src + m*128 + c);
    }
}

// ============================================================================
__global__ void k_rinv(const float* __restrict__ in){
    int nk = blockIdx.x, t = threadIdx.x;
    float v = in[(size_t)nk*MAT + t*D_B + t];
    g_rv[nk*D_B + t] = rsqrtf(fmaxf(fabsf(v), 1e-4f));
}

// fused cov2cor + channel mixing; cp.async double-buffered staging (frozen r15).
__global__ __launch_bounds__(256, 1) void k_mix(const float* __restrict__ inp,
                                                const float* __restrict__ wq,
                                                const float* __restrict__ wk){
    __shared__ float sWQ[C_B*C_B], sWK[C_B*C_B];
    __shared__ float sX [2][8*D_B];
    __shared__ float sRV[2][8*D_B];
    int tid = threadIdx.x, n = blockIdx.y, irow = blockIdx.x;
    int tx = tid & 31, ty = tid >> 5, k0 = ty*8;
    u32 sxA[2] = { smem_u32(&sX[0][0]),  smem_u32(&sX[1][0])  };
    u32 rvA[2] = { smem_u32(&sRV[0][0]), smem_u32(&sRV[1][0]) };

    {
        int cl = tid >> 5, jj = (tid & 31)*4;
        cp16(sxA[0] + (u32)((cl*D_B + jj)*4),
             inp + ((size_t)(n*C_B + cl))*MAT + irow*D_B + jj);
        int idx = tid*4, cl2 = idx >> 7, j2 = idx & 127;
        cp16(rvA[0] + (u32)(idx*4), g_rv + ((size_t)(n*C_B + cl2))*D_B + j2);
        cp_commit();
    }
    for (int i = tid; i < C_B*C_B; i += 256){ sWQ[i] = wq[i]; sWK[i] = wk[i]; }

    u64 aQ[4][4], aK[4][4];
    #pragma unroll
    for (int p = 0; p < 4; p++)
        #pragma unroll
        for (int q = 0; q < 4; q++){ aQ[p][q] = 0ull; aK[p][q] = 0ull; }

    for (int cb = 0; cb < 8; cb++){
        int cur = cb & 1, cc = cb*8;
        if (cb < 7){
            int nb = cur ^ 1, ncc = cc + 8;
            int cl = tid >> 5, jj = (tid & 31)*4;
            cp16(sxA[nb] + (u32)((cl*D_B + jj)*4),
                 inp + ((size_t)(n*C_B + ncc + cl))*MAT + irow*D_B + jj);
            int idx = tid*4, cl2 = idx >> 7, j2 = idx & 127;
            cp16(rvA[nb] + (u32)(idx*4), g_rv + ((size_t)(n*C_B + ncc + cl2))*D_B + j2);
            cp_commit();
            cp_wait1();
        } else {
            cp_wait0();
        }
        __syncthreads();
        {
            int cl = tid >> 5, jj = (tid & 31)*4;
            float4 v = *(float4*)&sX[cur][cl*D_B + jj];
            float ri = sRV[cur][cl*D_B + irow];
            v.x = clip1(v.x*ri*sRV[cur][cl*D_B + jj+0]);
            v.y = clip1(v.y*ri*sRV[cur][cl*D_B + jj+1]);
            v.z = clip1(v.z*ri*sRV[cur][cl*D_B + jj+2]);
            v.w = clip1(v.w*ri*sRV[cur][cl*D_B + jj+3]);
            *(float4*)&sX[cur][cl*D_B + jj] = v;
        }
        __syncthreads();
        #pragma unroll
        for (int cl = 0; cl < 8; cl++){
            int c = cc + cl;
            float4 xv = *(const float4*)&sX[cur][cl*D_B + tx*4];
            u64 xx[4] = { bcast2(xv.x), bcast2(xv.y), bcast2(xv.z), bcast2(xv.w) };
            F4U q0, q1, kk0, kk1;
            q0.f = *(const float4*)&sWQ[c*C_B + k0];  q1.f = *(const float4*)&sWQ[c*C_B + k0 + 4];
            kk0.f = *(const float4*)&sWK[c*C_B + k0]; kk1.f = *(const float4*)&sWK[c*C_B + k0 + 4];
            u64 bq[4] = { q0.u[0], q0.u[1], q1.u[0], q1.u[1] };
            u64 bk[4] = { kk0.u[0], kk0.u[1], kk1.u[0], kk1.u[1] };
            #pragma unroll
            for (int p = 0; p < 4; p++)
                #pragma unroll
                for (int q = 0; q < 4; q++){
                    aQ[p][q] = ffma2(xx[p], bq[q], aQ[p][q]);
                    aK[p][q] = ffma2(xx[p], bk[q], aK[p][q]);
                }
        }
        __syncthreads();
    }
    #pragma unroll
    for (int q = 0; q < 4; q++)
        #pragma unroll
        for (int h = 0; h < 2; h++){
            int k = k0 + q*2 + h;
            float vq[4], vk[4];
            #pragma unroll
            for (int p = 0; p < 4; p++){
                float lo, hi;
                unpack2(aQ[p][q], lo, hi); vq[p] = h ? hi : lo;
                unpack2(aK[p][q], lo, hi); vk[p] = h ? hi : lo;
            }
            size_t base = ((size_t)(n*C_B + k))*MAT + irow*D_B + tx*4;
            *(uint2*)&g_Qf[base] = make_uint2(cvt2h(vq[0], vq[1]), cvt2h(vq[2], vq[3]));
            *(uint2*)&g_Kf[base] = make_uint2(cvt2h(vk[0], vk[1]), cvt2h(vk[2], vk[3]));
        }
}

// ============================================================================
// k_attn: 256 threads, 3 fp16 tiles (104KB) -> 2 CTAs/SM for cross-CTA
// phase overlap. All matmuls fp16 single-product.
//   B0: Q -> X'''   B1: K -> P/32   B2: St -> e~
// ============================================================================
__global__ __launch_bounds__(TPB, 2) void k_attn(const float* __restrict__ inp,
                                                 const float* __restrict__ lam,
                                                 float* __restrict__ out){
    extern __shared__ char smc[];
    u32 sb = smem_u32(smc);
    u32 B0 = sb, B1 = sb + TILEB, B2 = sb + 2*TILEB;
    __shared__ float s_rv[D_B], s_sr[D_B], s_dia[D_B], s_part[D_B][4], s_red[12];
    int tid = threadIdx.x, w = tid >> 5, l = tid & 31;
    int wm = w >> 2, wn = w & 3;
    int r0 = l >> 2, c0 = (l & 3)*2;
    int nk = blockIdx.x;
    size_t gb = (size_t)nk * MAT;

    pf_tile(B0, g_Qf + gb, tid);
    pf_tile(B1, g_Kf + gb, tid);
    cp_commit();
    if (tid < D_B) s_rv[tid] = g_rv[nk*D_B + tid];
    cp_wait0();
    __syncthreads();

    float acc[4][4][4];
    wmm_h(B0, B1, 1, 1, wm, wn, l, acc);       // St = Q^T K
    store_acc_h(smc, B2 - sb, wm, wn, l, acc, 0, 1.0f);
    __syncthreads();                           // St ready; B0 (Q) dead

    wmm_h(B2, B1, 1, 1, wm, wn, l, acc);       // Apre = St^T K
    float mx = -3.4e38f;
    #pragma unroll
    for (int mt = 0; mt < 4; mt++)
        #pragma unroll
        for (int nt = 0; nt < 4; nt++)
            #pragma unroll
            for (int q = 0; q < 4; q++) mx = fmaxf(mx, acc[mt][nt][q]);
    #pragma unroll
    for (int o = 16; o; o >>= 1) mx = fmaxf(mx, __shfl_xor_sync(0xffffffffu, mx, o));
    if (l == 0) s_red[w] = mx;
    __syncthreads();                           // B1 (K) reads done
    if (tid == 0){
        float m2 = s_red[0];
        #pragma unroll
        for (int q = 1; q < 8; q++) m2 = fmaxf(m2, s_red[q]);
        s_red[8] = m2;
    }
    __syncthreads();
    float bmax = s_red[8];
    {   // exp (all-poly, fma pipe) in place + row partial sums
        const u64 kL2E = bcast2(1.4426950408889634f), kMAG = bcast2(12582912.0f),
                  kNMAG = bcast2(-12582912.0f), kN1 = bcast2(-1.0f),
                  kC5 = bcast2(1.3333558146e-3f), kC4 = bcast2(9.6181291076e-3f),
                  kC3 = bcast2(5.5504108664e-2f), kC2 = bcast2(2.4022650695e-1f),
                  kC1 = bcast2(6.9314718055e-1f), kONE = bcast2(1.0f),
                  kNB = bcast2(-bmax);
        float part[4][2] = {};
        #pragma unroll
        for (int mt = 0; mt < 4; mt++)
            #pragma unroll
            for (int nt = 0; nt < 4; nt++){
                u64 p0 = exp_pair(add2(pack2(acc[mt][nt][0], acc[mt][nt][1]), kNB),
                                  kL2E,kMAG,kNMAG,kN1,kC5,kC4,kC3,kC2,kC1,kONE);
                u64 p1 = exp_pair(add2(pack2(acc[mt][nt][2], acc[mt][nt][3]), kNB),
                                  kL2E,kMAG,kNMAG,kN1,kC5,kC4,kC3,kC2,kC1,kONE);
                unpack2(p0, acc[mt][nt][0], acc[mt][nt][1]);
                unpack2(p1, acc[mt][nt][2], acc[mt][nt][3]);
                part[mt][0] += acc[mt][nt][0] + acc[mt][nt][1];
                part[mt][1] += acc[mt][nt][2] + acc[mt][nt][3];
            }
        #pragma unroll
        for (int mt = 0; mt < 4; mt++)
            #pragma unroll
            for (int h = 0; h < 2; h++){
                float t = part[mt][h];
                t += __shfl_xor_sync(0xffffffffu, t, 1);
                t += __shfl_xor_sync(0xffffffffu, t, 2);
                if ((l & 3) == 0) s_part[wm*64 + mt*16 + h*8 + r0][wn] = t;
            }
    }
    // X''' = clip(inp*rv_i*rv_j) straight from gmem -> B0 (fp16, over Q)
    for (int e = tid; e < 4096; e += TPB){
        int i = e >> 5, j = (e & 31)*4;
        float4 v = *(const float4*)&inp[gb + i*128 + j];
        float ri = s_rv[i];
        v.x = clip1(v.x*ri*s_rv[j+0]); v.y = clip1(v.y*ri*s_rv[j+1]);
        v.z = clip1(v.z*ri*s_rv[j+2]); v.w = clip1(v.w*ri*s_rv[j+3]);
        u32 off = (B0 - sb) + (u32)((i*SSTR + j)*2);
        *(u32*)(smc + off)     = cvt2h(v.x, v.y);
        *(u32*)(smc + off + 4) = cvt2h(v.z, v.w);
    }
    __syncthreads();
    if (tid < D_B)
        s_dia[tid] = s_part[tid][0] + s_part[tid][1] + s_part[tid][2] + s_part[tid][3];
    __syncthreads();
    if (tid < 32){
        float t = s_dia[tid] + s_dia[tid+32] + s_dia[tid+64] + s_dia[tid+96];
        #pragma unroll
        for (int o = 16; o; o >>= 1) t += __shfl_xor_sync(0xffffffffu, t, o);
        if (tid == 0) s_red[9] = t;
    }
    __syncthreads();
    if (tid < D_B){
        float d = fmaxf(fmaxf(s_dia[tid], s_red[9]/100000.0f), 1e-5f);
        s_sr[tid] = rsqrtf(d);
    }
    __syncthreads();
    store_acc_h(smc, B2 - sb, wm, wn, l, acc, s_sr, 1.0f);  // e~ = e*sr_col (over St)
    __syncthreads();

    wmm_h(B2, B0, 0, 1, wm, wn, l, acc);       // P = e~ X'''
    __syncthreads();                           // X'''/K reads done; B1 free
    store_acc_h(smc, B1 - sb, wm, wn, l, acc, 0, PSCL);  // P/32 -> B1
    __syncthreads();

    wmm_h(B1, B2, 0, 0, wm, wn, l, acc);       // O = (P/32) e~^T
    {   // epilogue: out = inp + lam*32*sr_i*sr_j*O
        float lamv = lam[nk & (C_B - 1)] * PSCLI;
        #pragma unroll
        for (int mt = 0; mt < 4; mt++)
            #pragma unroll
            for (int nt = 0; nt < 4; nt++){
                int row = wm*64 + mt*16 + r0, col = wn*32 + nt*8 + c0;
                float sc0 = s_sr[col], sc1 = s_sr[col+1];
                #pragma unroll
                for (int h = 0; h < 2; h++){
                    int rr = row + h*8;
                    float li = lamv * s_sr[rr];
                    float2 iv = *(const float2*)&inp[gb + rr*128 + col];
                    float2 o;
                    o.x = iv.x + li*sc0*acc[mt][nt][h*2+0];
                    o.y = iv.y + li*sc1*acc[mt][nt][h*2+1];
                    *(float2*)&out[gb + rr*128 + col] = o;
                }
            }
    }
}

// ============================================================================
extern "C" void kernel_launch(void* const* d_in, const int* in_sizes, int n_in,
                              void* d_out, int out_size){
    const float* inp = (const float*)d_in[0];
    const float* wq  = (const float*)d_in[1];
    const float* wk  = (const float*)d_in[2];
    const float* lam = (const float*)d_in[3];
    float* out = (float*)d_out;

    cudaFuncSetAttribute(k_attn, cudaFuncAttributeMaxDynamicSharedMemorySize, DSM3);

    k_rinv<<<NK_TOT, D_B>>>(inp);
    k_mix<<<dim3(D_B, N_B), 256>>>(inp, wq, wk);
    k_attn<<<NK_TOT, TPB, DSM3>>>(inp, lam, out);
}

// round 17
// speedup vs baseline: 1.5243x; 1.1693x over previous
#include <cuda_runtime.h>
#include <cuda_bf16.h>

#define N_B 32
#define C_B 64
#define D_B 128
#define MAT 16384
#define NK_TOT 2048
#define TPB 256

// fp16 tile geometry
#define SSTR 136                 // halves per row (272B, conflict-free for ldmatrix)
#define TILEB 34816              // one 128x136 b16 tile (k_attn)
#define DSM3 (3*TILEB)           // 104448 B dynamic smem -> 2 CTAs/SM (k_attn)
#define MTILE (64*SSTR*2)        // 17408 B: one 64x136 fp16 tile (k_mix)
#define DSMX (3*MTILE)           // 52224 B dynamic smem -> 2 CTAs/SM (k_mix)
#define PSCL 0.03125f
#define PSCLI 32.0f

typedef unsigned long long u64;
typedef unsigned int u32;
typedef unsigned short u16;

__device__ float g_rv[NK_TOT*D_B];
__device__ u16 g_Qf[NK_TOT*MAT], g_Kf[NK_TOT*MAT];

// ---------- f32x2 helpers ----------
__device__ __forceinline__ u64 bcast2(float x){
    u64 r; asm("mov.b64 %0, {%1, %1};" : "=l"(r) : "r"(__float_as_uint(x))); return r;
}
__device__ __forceinline__ u64 pack2(float a, float b){
    u64 r; asm("mov.b64 %0, {%1, %2};" : "=l"(r) : "r"(__float_as_uint(a)), "r"(__float_as_uint(b))); return r;
}
__device__ __forceinline__ u64 ffma2(u64 a, u64 b, u64 c){
    u64 d; asm("fma.rn.f32x2 %0, %1, %2, %3;" : "=l"(d) : "l"(a), "l"(b), "l"(c)); return d;
}
__device__ __forceinline__ u64 add2(u64 a, u64 b){
    u64 d; asm("add.rn.f32x2 %0, %1, %2;" : "=l"(d) : "l"(a), "l"(b)); return d;
}
__device__ __forceinline__ u64 mul2(u64 a, u64 b){
    u64 d; asm("mul.rn.f32x2 %0, %1, %2;" : "=l"(d) : "l"(a), "l"(b)); return d;
}
__device__ __forceinline__ void unpack2(u64 v, float& lo, float& hi){
    u32 a, b; asm("mov.b64 {%0, %1}, %2;" : "=r"(a), "=r"(b) : "l"(v));
    lo = __uint_as_float(a); hi = __uint_as_float(b);
}
__device__ __forceinline__ void unpack2u(u64 v, u32& a, u32& b){
    asm("mov.b64 {%0, %1}, %2;" : "=r"(a), "=r"(b) : "l"(v));
}
__device__ __forceinline__ float clip1(float x){ return fminf(1.f, fmaxf(-1.f, x)); }

// fma-pipe exp (magic rounding + deg-5 Taylor), underflow-clamped
__device__ __forceinline__ u64 exp_pair(u64 xb, u64 kL2E, u64 kMAG, u64 kNMAG, u64 kN1,
                                        u64 kC5, u64 kC4, u64 kC3, u64 kC2, u64 kC1, u64 kONE){
    u64 y = mul2(xb, kL2E);
    u64 z = add2(y, kMAG);
    u64 t = add2(z, kNMAG);
    u64 f = ffma2(t, kN1, y);
    u64 p = ffma2(kC5, f, kC4);
    p = ffma2(p, f, kC3); p = ffma2(p, f, kC2); p = ffma2(p, f, kC1); p = ffma2(p, f, kONE);
    u32 zl, zh; unpack2u(z, zl, zh);
    int n0 = max((int)(zl - 0x4B400000u), -127), n1 = max((int)(zh - 0x4B400000u), -127);
    u64 s; asm("mov.b64 %0, {%1, %2};" : "=l"(s)
               : "r"((u32)(n0 + 127) << 23), "r"((u32)(n1 + 127) << 23));
    return mul2(p, s);
}

// ---------- async / mma primitives ----------
__device__ __forceinline__ void cp16(u32 s, const void* g){
    asm volatile("cp.async.cg.shared.global [%0], [%1], 16;" :: "r"(s), "l"(g));
}
__device__ __forceinline__ void cp_commit(){ asm volatile("cp.async.commit_group;"); }
__device__ __forceinline__ void cp_wait0(){ asm volatile("cp.async.wait_group 0;"); }
__device__ __forceinline__ u32 smem_u32(const void* p){
    u32 a; asm("{ .reg .u64 t; cvta.to.shared.u64 t, %1; cvt.u32.u64 %0, t; }" : "=r"(a) : "l"(p));
    return a;
}
__device__ __forceinline__ void ldsm4(u32 a, u32* r){
    asm volatile("ldmatrix.sync.aligned.m8n8.x4.shared.b16 {%0,%1,%2,%3}, [%4];"
        : "=r"(r[0]), "=r"(r[1]), "=r"(r[2]), "=r"(r[3]) : "r"(a));
}
__device__ __forceinline__ void ldsm4t(u32 a, u32* r){
    asm volatile("ldmatrix.sync.aligned.m8n8.x4.trans.shared.b16 {%0,%1,%2,%3}, [%4];"
        : "=r"(r[0]), "=r"(r[1]), "=r"(r[2]), "=r"(r[3]) : "r"(a));
}
__device__ __forceinline__ void ldsm2(u32 a, u32* r){
    asm volatile("ldmatrix.sync.aligned.m8n8.x2.shared.b16 {%0,%1}, [%2];"
        : "=r"(r[0]), "=r"(r[1]) : "r"(a));
}
__device__ __forceinline__ void ldsm2t(u32 a, u32* r){
    asm volatile("ldmatrix.sync.aligned.m8n8.x2.trans.shared.b16 {%0,%1}, [%2];"
        : "=r"(r[0]), "=r"(r[1]) : "r"(a));
}
__device__ __forceinline__ void mmah(float* d, const u32* a, const u32* b){
    asm volatile("mma.sync.aligned.m16n8k16.row.col.f32.f16.f16.f32 "
        "{%0,%1,%2,%3},{%4,%5,%6,%7},{%8,%9},{%0,%1,%2,%3};"
        : "+f"(d[0]), "+f"(d[1]), "+f"(d[2]), "+f"(d[3])
        : "r"(a[0]), "r"(a[1]), "r"(a[2]), "r"(a[3]), "r"(b[0]), "r"(b[1]));
}
__device__ __forceinline__ u32 cvt2h(float lo, float hi){
    u32 r; asm("cvt.rn.f16x2.f32 %0, %1, %2;" : "=r"(r) : "f"(hi), "f"(lo)); return r;
}

// warp-tile fp16 matmul, 64x32 warp tile (8 warps, 2x4 grid): acc[4][4][4].
__device__ __forceinline__ void wmm_h(u32 aB, u32 bB, int am, int bm,
                                      int wm, int wn, int l, float acc[4][4][4]){
    #pragma unroll
    for (int mt = 0; mt < 4; mt++)
        #pragma unroll
        for (int nt = 0; nt < 4; nt++)
            #pragma unroll
            for (int q = 0; q < 4; q++) acc[mt][nt][q] = 0.f;
    #pragma unroll
    for (int ks = 0; ks < 8; ks++){
        int k0 = ks*16;
        u32 Ah[4][4], Bh[4][2];
        #pragma unroll
        for (int mt = 0; mt < 4; mt++){
            int i0 = wm*64 + mt*16;
            u32 ad;
            if (am == 0) ad = aB + (u32)(((i0 + (l&7) + ((l>>3)&1)*8)*SSTR + k0 + (l>>4)*8)*2);
            else         ad = aB + (u32)(((k0 + (l>>4)*8 + (l&7))*SSTR + i0 + ((l>>3)&1)*8)*2);
            if (am == 0) ldsm4(ad, Ah[mt]);
            else         ldsm4t(ad, Ah[mt]);
        }
        #pragma unroll
        for (int nt = 0; nt < 4; nt++){
            int j0 = wn*32 + nt*8;
            u32 bd;
            if (bm == 0) bd = bB + (u32)(((j0 + (l&7))*SSTR + k0 + ((l>>3)&1)*8)*2);
            else         bd = bB + (u32)(((k0 + (l&15))*SSTR + j0)*2);
            if (bm == 0) ldsm2(bd, Bh[nt]);
            else         ldsm2t(bd, Bh[nt]);
        }
        #pragma unroll
        for (int mt = 0; mt < 4; mt++)
            #pragma unroll
            for (int nt = 0; nt < 4; nt++)
                mmah(acc[mt][nt], Ah[mt], Bh[nt]);
    }
}

// store warp acc -> single fp16 tile, optional per-column scale + global scale
__device__ __forceinline__ void store_acc_h(char* smc, u32 dstOff, int wm, int wn, int l,
                                            float acc[4][4][4], const float* colscale,
                                            float gs){
    int r0 = l >> 2, c0 = (l & 3)*2;
    #pragma unroll
    for (int mt = 0; mt < 4; mt++)
        #pragma unroll
        for (int nt = 0; nt < 4; nt++){
            int row = wm*64 + mt*16 + r0, col = wn*32 + nt*8 + c0;
            float s0 = gs, s1 = gs;
            if (colscale){ s0 *= colscale[col]; s1 *= colscale[col+1]; }
            #pragma unroll
            for (int h = 0; h < 2; h++){
                u32 hp = cvt2h(acc[mt][nt][h*2] * s0, acc[mt][nt][h*2+1] * s1);
                *(u32*)(smc + dstOff + (u32)((((row + h*8)*SSTR) + col)*2)) = hp;
            }
        }
}

__device__ __forceinline__ void pf_tile(u32 dst, const u16* __restrict__ src, int tid){
    for (int g = tid; g < 2048; g += TPB){
        int m = g >> 4, c = (g & 15)*8;
        cp16(dst + (u32)((m*SSTR + c)*2), src + m*128 + c);
    }
}

// ============================================================================
__global__ void k_rinv(const float* __restrict__ in){
    int nk = blockIdx.x, t = threadIdx.x;
    float v = in[(size_t)nk*MAT + t*D_B + t];
    g_rv[nk*D_B + t] = rsqrtf(fmaxf(fabsf(v), 1e-4f));
}

// ============================================================================
// k_mix (HMMA): out[k][j] = sum_c W[c][k] * X'[c][j], X' = clip(cov2cor) fp16.
// Block = (i-row, n). smem: sA = X' [c][j] 64x136; sWq/sWk = W [c][k] 64x136.
// A operand = W (am=1 pattern, frags hoisted); B operand = X' (bm=1 pattern).
// Warps 0-3 -> Q (k-tile = w), warps 4-7 -> K. Two 64-col j passes.
// ============================================================================
__global__ __launch_bounds__(256, 2) void k_mix(const float* __restrict__ inp,
                                                const float* __restrict__ wq,
                                                const float* __restrict__ wk){
    extern __shared__ char smx[];
    u32 sb = smem_u32(smx);
    u32 A_ = sb, Wq_ = sb + MTILE, Wk_ = sb + 2*MTILE;
    int tid = threadIdx.x, w = tid >> 5, l = tid & 31;
    int n = blockIdx.y, irow = blockIdx.x;

    // load W (both) fp32 -> fp16, natural [c][k] layout
    for (int e = tid; e < 2048; e += 256){
        int c = e >> 5, k = (e & 31)*2;
        float2 vq = *(const float2*)&wq[c*C_B + k];
        float2 vk = *(const float2*)&wk[c*C_B + k];
        u32 off = (u32)((c*SSTR + k)*2);
        *(u32*)(smx + (Wq_ - sb) + off) = cvt2h(vq.x, vq.y);
        *(u32*)(smx + (Wk_ - sb) + off) = cvt2h(vk.x, vk.y);
    }
    // load + transform X' = clip(inp*rv_i*rv_j) -> sA [c][j] fp16
    for (int e = tid; e < 2048; e += 256){
        int c = e >> 5, j = (e & 31)*4;
        const float* src = inp + ((size_t)(n*C_B + c))*MAT + irow*D_B + j;
        float4 v = *(const float4*)src;
        float ri = g_rv[(n*C_B + c)*D_B + irow];
        float4 rj = *(const float4*)&g_rv[(n*C_B + c)*D_B + j];
        v.x = clip1(v.x*ri*rj.x); v.y = clip1(v.y*ri*rj.y);
        v.z = clip1(v.z*ri*rj.z); v.w = clip1(v.w*ri*rj.w);
        u32 off = (u32)((c*SSTR + j)*2);
        *(u32*)(smx + off)     = cvt2h(v.x, v.y);
        *(u32*)(smx + off + 4) = cvt2h(v.z, v.w);
    }
    __syncthreads();

    int t  = w >> 2;                 // 0 = Q, 1 = K
    int kt = w & 3;                  // k-tile (16 rows of k)
    u32 wbase = t ? Wk_ : Wq_;
    u16* gout = t ? g_Kf : g_Qf;
    int k0m = kt*16;

    // A fragments (W), hoisted across both passes: 4 csteps x 4 regs
    u32 Af[4][4];
    #pragma unroll
    for (int cs = 0; cs < 4; cs++){
        u32 ad = wbase + (u32)(((cs*16 + (l>>4)*8 + (l&7))*SSTR + k0m + ((l>>3)&1)*8)*2);
        ldsm4t(ad, Af[cs]);
    }

    int r0 = l >> 2, c0 = (l & 3)*2;
    #pragma unroll
    for (int pass = 0; pass < 2; pass++){
        float acc[8][4];
        #pragma unroll
        for (int nt = 0; nt < 8; nt++)
            #pragma unroll
            for (int q = 0; q < 4; q++) acc[nt][q] = 0.f;
        #pragma unroll
        for (int cs = 0; cs < 4; cs++){
            u32 Bf[8][2];
            #pragma unroll
            for (int nt = 0; nt < 8; nt++){
                int j0 = pass*64 + nt*8;
                u32 bd = A_ + (u32)(((cs*16 + (l&15))*SSTR + j0)*2);
                ldsm2t(bd, Bf[nt]);
            }
            #pragma unroll
            for (int nt = 0; nt < 8; nt++)
                mmah(acc[nt], Af[cs], Bf[nt]);
        }
        #pragma unroll
        for (int nt = 0; nt < 8; nt++)
            #pragma unroll
            for (int h = 0; h < 2; h++){
                int k = k0m + r0 + h*8;
                int j = pass*64 + nt*8 + c0;
                u32 hp = cvt2h(acc[nt][h*2], acc[nt][h*2+1]);
                *(u32*)&gout[((size_t)(n*C_B + k))*MAT + irow*D_B + j] = hp;
            }
    }
}

// ============================================================================
// k_attn: FROZEN from round 16 (2 CTAs/SM, fp16-everywhere).
// ============================================================================
__global__ __launch_bounds__(TPB, 2) void k_attn(const float* __restrict__ inp,
                                                 const float* __restrict__ lam,
                                                 float* __restrict__ out){
    extern __shared__ char smc[];
    u32 sb = smem_u32(smc);
    u32 B0 = sb, B1 = sb + TILEB, B2 = sb + 2*TILEB;
    __shared__ float s_rv[D_B], s_sr[D_B], s_dia[D_B], s_part[D_B][4], s_red[12];
    int tid = threadIdx.x, w = tid >> 5, l = tid & 31;
    int wm = w >> 2, wn = w & 3;
    int r0 = l >> 2, c0 = (l & 3)*2;
    int nk = blockIdx.x;
    size_t gb = (size_t)nk * MAT;

    pf_tile(B0, g_Qf + gb, tid);
    pf_tile(B1, g_Kf + gb, tid);
    cp_commit();
    if (tid < D_B) s_rv[tid] = g_rv[nk*D_B + tid];
    cp_wait0();
    __syncthreads();

    float acc[4][4][4];
    wmm_h(B0, B1, 1, 1, wm, wn, l, acc);       // St = Q^T K
    store_acc_h(smc, B2 - sb, wm, wn, l, acc, 0, 1.0f);
    __syncthreads();

    wmm_h(B2, B1, 1, 1, wm, wn, l, acc);       // Apre = St^T K
    float mx = -3.4e38f;
    #pragma unroll
    for (int mt = 0; mt < 4; mt++)
        #pragma unroll
        for (int nt = 0; nt < 4; nt++)
            #pragma unroll
            for (int q = 0; q < 4; q++) mx = fmaxf(mx, acc[mt][nt][q]);
    #pragma unroll
    for (int o = 16; o; o >>= 1) mx = fmaxf(mx, __shfl_xor_sync(0xffffffffu, mx, o));
    if (l == 0) s_red[w] = mx;
    __syncthreads();
    if (tid == 0){
        float m2 = s_red[0];
        #pragma unroll
        for (int q = 1; q < 8; q++) m2 = fmaxf(m2, s_red[q]);
        s_red[8] = m2;
    }
    __syncthreads();
    float bmax = s_red[8];
    {
        const u64 kL2E = bcast2(1.4426950408889634f), kMAG = bcast2(12582912.0f),
                  kNMAG = bcast2(-12582912.0f), kN1 = bcast2(-1.0f),
                  kC5 = bcast2(1.3333558146e-3f), kC4 = bcast2(9.6181291076e-3f),
                  kC3 = bcast2(5.5504108664e-2f), kC2 = bcast2(2.4022650695e-1f),
                  kC1 = bcast2(6.9314718055e-1f), kONE = bcast2(1.0f),
                  kNB = bcast2(-bmax);
        float part[4][2] = {};
        #pragma unroll
        for (int mt = 0; mt < 4; mt++)
            #pragma unroll
            for (int nt = 0; nt < 4; nt++){
                u64 p0 = exp_pair(add2(pack2(acc[mt][nt][0], acc[mt][nt][1]), kNB),
                                  kL2E,kMAG,kNMAG,kN1,kC5,kC4,kC3,kC2,kC1,kONE);
                u64 p1 = exp_pair(add2(pack2(acc[mt][nt][2], acc[mt][nt][3]), kNB),
                                  kL2E,kMAG,kNMAG,kN1,kC5,kC4,kC3,kC2,kC1,kONE);
                unpack2(p0, acc[mt][nt][0], acc[mt][nt][1]);
                unpack2(p1, acc[mt][nt][2], acc[mt][nt][3]);
                part[mt][0] += acc[mt][nt][0] + acc[mt][nt][1];
                part[mt][1] += acc[mt][nt][2] + acc[mt][nt][3];
            }
        #pragma unroll
        for (int mt = 0; mt < 4; mt++)
            #pragma unroll
            for (int h = 0; h < 2; h++){
                float t = part[mt][h];
                t += __shfl_xor_sync(0xffffffffu, t, 1);
                t += __shfl_xor_sync(0xffffffffu, t, 2);
                if ((l & 3) == 0) s_part[wm*64 + mt*16 + h*8 + r0][wn] = t;
            }
    }
    for (int e = tid; e < 4096; e += TPB){
        int i = e >> 5, j = (e & 31)*4;
        float4 v = *(const float4*)&inp[gb + i*128 + j];
        float ri = s_rv[i];
        v.x = clip1(v.x*ri*s_rv[j+0]); v.y = clip1(v.y*ri*s_rv[j+1]);
        v.z = clip1(v.z*ri*s_rv[j+2]); v.w = clip1(v.w*ri*s_rv[j+3]);
        u32 off = (B0 - sb) + (u32)((i*SSTR + j)*2);
        *(u32*)(smc + off)     = cvt2h(v.x, v.y);
        *(u32*)(smc + off + 4) = cvt2h(v.z, v.w);
    }
    __syncthreads();
    if (tid < D_B)
        s_dia[tid] = s_part[tid][0] + s_part[tid][1] + s_part[tid][2] + s_part[tid][3];
    __syncthreads();
    if (tid < 32){
        float t = s_dia[tid] + s_dia[tid+32] + s_dia[tid+64] + s_dia[tid+96];
        #pragma unroll
        for (int o = 16; o; o >>= 1) t += __shfl_xor_sync(0xffffffffu, t, o);
        if (tid == 0) s_red[9] = t;
    }
    __syncthreads();
    if (tid < D_B){
        float d = fmaxf(fmaxf(s_dia[tid], s_red[9]/100000.0f), 1e-5f);
        s_sr[tid] = rsqrtf(d);
    }
    __syncthreads();
    store_acc_h(smc, B2 - sb, wm, wn, l, acc, s_sr, 1.0f);
    __syncthreads();

    wmm_h(B2, B0, 0, 1, wm, wn, l, acc);       // P = e~ X'''
    __syncthreads();
    store_acc_h(smc, B1 - sb, wm, wn, l, acc, 0, PSCL);
    __syncthreads();

    wmm_h(B1, B2, 0, 0, wm, wn, l, acc);       // O = (P/32) e~^T
    {
        float lamv = lam[nk & (C_B - 1)] * PSCLI;
        #pragma unroll
        for (int mt = 0; mt < 4; mt++)
            #pragma unroll
            for (int nt = 0; nt < 4; nt++){
                int row = wm*64 + mt*16 + r0, col = wn*32 + nt*8 + c0;
                float sc0 = s_sr[col], sc1 = s_sr[col+1];
                #pragma unroll
                for (int h = 0; h < 2; h++){
                    int rr = row + h*8;
                    float li = lamv * s_sr[rr];
                    float2 iv = *(const float2*)&inp[gb + rr*128 + col];
                    float2 o;
                    o.x = iv.x + li*sc0*acc[mt][nt][h*2+0];
                    o.y = iv.y + li*sc1*acc[mt][nt][h*2+1];
                    *(float2*)&out[gb + rr*128 + col] = o;
                }
            }
    }
}

// ============================================================================
extern "C" void kernel_launch(void* const* d_in, const int* in_sizes, int n_in,
                              void* d_out, int out_size){
    const float* inp = (const float*)d_in[0];
    const float* wq  = (const float*)d_in[1];
    const float* wk  = (const float*)d_in[2];
    const float* lam = (const float*)d_in[3];
    float* out = (float*)d_out;

    cudaFuncSetAttribute(k_attn, cudaFuncAttributeMaxDynamicSharedMemorySize, DSM3);
    cudaFuncSetAttribute(k_mix,  cudaFuncAttributeMaxDynamicSharedMemorySize, DSMX);

    k_rinv<<<NK_TOT, D_B>>>(inp);
    k_mix<<<dim3(D_B, N_B), 256, DSMX>>>(inp, wq, wk);
    k_attn<<<NK_TOT, TPB, DSM3>>>(inp, lam, out);
}